// round 10
// baseline (speedup 1.0000x reference)
#include <cuda_runtime.h>

typedef unsigned long long ull;

// ---------------------------------------------------------------------------
// Problem constants
// ---------------------------------------------------------------------------
namespace {
constexpr int Bn  = 2048;
constexpr int Sn  = 200;
constexpr int Tn  = 50;
constexpr int INn = 44;
constexpr int Hn  = 128;
constexpr int Ln  = 4;
constexpr long BH = (long)Bn * Hn;            // 262144 elems per (B,H) slab

// packed weights: per matrix 8 jb-tiles * K rows * 128 floats
constexpr long PK_IH0 = 8L * 44  * 128;       // 45056
constexpr long PK_128 = 8L * 128 * 128;       // 131072
constexpr long OFF_EIH0 = 0;
constexpr long OFF_EIHR = OFF_EIH0 + PK_IH0;
constexpr long OFF_EHH  = OFF_EIHR + 3 * PK_128;
constexpr long OFF_DIH0 = OFF_EHH  + 4 * PK_128;
constexpr long OFF_DIHR = OFF_DIH0 + PK_IH0;
constexpr long OFF_DHH  = OFF_DIHR + 3 * PK_128;
constexpr long PK_TOTAL = OFF_DHH  + 4 * PK_128;

constexpr int PITCH = 132;                    // sA pitch in floats (16B-aligned rows)
}

// ---------------------------------------------------------------------------
// Scratch (static device globals; no runtime allocation allowed)
// ---------------------------------------------------------------------------
__device__ float g_ysA[(long)Sn * Bn * Hn];       // 209.7 MB
__device__ float g_ysB[(long)Sn * Bn * Hn];       // 209.7 MB
__device__ float g_encC[(long)Ln * Bn * Hn];      // final cell state per enc layer
__device__ float g_decH[2L * Ln * Bn * Hn];       // decoder h ping-pong [2][L][B][H]
__device__ float g_out2[2L * Bn * INn];           // decoder output ping-pong
__device__ float g_wpk[PK_TOTAL];
__device__ unsigned g_barc[16];                   // per-mt barrier counters (zero-init)
__device__ unsigned g_bars[16];                   // per-mt barrier sense

// ---------------------------------------------------------------------------
// f32x2 helpers (sm_103a packed fp32 FMA)
// ---------------------------------------------------------------------------
__device__ __forceinline__ ull pk2(float x, float y) {
    ull r; asm("mov.b64 %0, {%1, %2};" : "=l"(r) : "f"(x), "f"(y)); return r;
}
__device__ __forceinline__ float2 upk(ull v) {
    float2 r; asm("mov.b64 {%0, %1}, %2;" : "=f"(r.x), "=f"(r.y) : "l"(v)); return r;
}
__device__ __forceinline__ void fmax2(ull& d, ull a, ull b) {
    asm("fma.rn.f32x2 %0, %1, %2, %0;" : "+l"(d) : "l"(a), "l"(b));
}
__device__ __forceinline__ float sigf(float x) {
    return __fdividef(1.f, 1.f + __expf(-x));
}
__device__ __forceinline__ float tanh_f(float x) {
    float xc = fminf(fmaxf(x, -15.f), 15.f);
    float e = __expf(2.f * xc);
    return __fdividef(e - 1.f, e + 1.f);
}

// ---------------------------------------------------------------------------
// mt-local barrier among the 8 CTAs sharing a batch-row tile (sense-reversing)
// ---------------------------------------------------------------------------
__device__ __forceinline__ void mt_barrier(int mt, unsigned* s_sense) {
    __threadfence();
    __syncthreads();
    if (threadIdx.x == 0) {
        unsigned ns = *s_sense ^ 1u;
        *s_sense = ns;
        unsigned a = atomicAdd(&g_barc[mt], 1u);
        if (a == 7u) {
            g_barc[mt] = 0u;
            __threadfence();
            atomicExch(&g_bars[mt], ns);
        } else {
            volatile unsigned* p = &g_bars[mt];
            while (*p != ns) __nanosleep(64);
            __threadfence();
        }
    }
    __syncthreads();
}

// ---------------------------------------------------------------------------
// Weight pre-pack:
// W (512 x K row-major, rows = gate*128 + j) ->
// Wpk[(jb*K + k)*128 + hu*8 + g*2 + dup]   (dup 0/1 identical; g in {i,f,g,o})
// so one LDS.128 at hu*8 yields (i,i,f,f); next yields (g,g,o,o).
// ---------------------------------------------------------------------------
__global__ void pack_w_kernel(const float* __restrict__ W, float* __restrict__ Wpk, int K) {
    int idx = blockIdx.x * blockDim.x + threadIdx.x;
    int total = 8 * K * 128;
    if (idx >= total) return;
    int inner = idx & 127;
    int rem   = idx >> 7;              // jb*K + k
    int k  = rem % K;
    int jb = rem / K;
    int hu = inner >> 3;
    int ge = (inner >> 1) & 3;
    Wpk[idx] = W[(long)(ge * 128 + jb * 16 + hu) * K + k];
}

// ---------------------------------------------------------------------------
// Persistent encoder layer kernel.
// grid = 128 CTAs: mt = bx>>3 (16 tiles of 128 batch rows), jb = bx&7 (16 units).
// 256 threads: hu = tid&15, mg = tid>>4 (16 groups of 8 rows).
// Weights (K1p+128 rows x 128 floats) resident in dynamic smem.
// c kept in registers for all S steps; h via global + mt-barrier.
// ---------------------------------------------------------------------------
__global__ __launch_bounds__(256, 1) void enc_layer_kernel(
    const float* __restrict__ A1, long lda1, long stepA1, int K1, int K1p,
    const float* __restrict__ Wpk1, const float* __restrict__ Wpk2,
    const float* __restrict__ bias,
    float* __restrict__ ysOut, float* __restrict__ hFinal, float* __restrict__ cFinal)
{
    extern __shared__ float sm[];
    const int Ktp = K1p + 128;
    float* sW  = sm;                       // Ktp*128 floats
    float* sA0 = sm + (long)Ktp * 128;     // 16*PITCH
    float* sA1 = sA0 + 16 * PITCH;
    __shared__ unsigned s_sense;

    int tid = threadIdx.x;
    int bx  = blockIdx.x;
    int mt = bx >> 3, jb = bx & 7;
    int m0 = mt * 128;
    int hu = tid & 15, mg = tid >> 4;
    int mg8 = mg * 8;
    int j = jb * 16 + hu;

    if (tid == 0) s_sense = *(volatile unsigned*)&g_bars[mt];

    // ---- load resident weights (once) ----
    {
        const float4* w1 = (const float4*)(Wpk1 + (long)jb * K1 * 128);
        int n1 = K1p * 32;                 // float4 count incl. zero pad rows
        for (int i = tid; i < n1; i += 256) {
            float4 v = make_float4(0.f, 0.f, 0.f, 0.f);
            if ((i >> 5) < K1) v = w1[i];
            ((float4*)sW)[i] = v;
        }
        const float4* w2 = (const float4*)(Wpk2 + (long)jb * 128 * 128);
        float4* d2 = (float4*)(sW + (long)K1p * 128);
        for (int i = tid; i < 128 * 32; i += 256) d2[i] = w2[i];
    }
    __syncthreads();

    float bi = bias[j], bf = bias[128 + j], bg = bias[256 + j], bo = bias[384 + j];
    float creg[8];
    #pragma unroll
    for (int i = 0; i < 8; i++) creg[i] = 0.f;

    const int nch = Ktp >> 4;

    for (int t = 0; t < Sn; t++) {
        ull accI[4], accF[4], accG[4], accO[4];
        #pragma unroll
        for (int p = 0; p < 4; p++) {
            accI[p] = pk2(bi, bi); accF[p] = pk2(bf, bf);
            accG[p] = pk2(bg, bg); accO[p] = pk2(bo, bo);
        }
        const float* hprev = ysOut + (long)(t - 1) * BH;   // valid iff t>0
        long aoff = (long)t * stepA1;

        float4 pf0, pf1;
        auto issue = [&](int kc) {
            #pragma unroll
            for (int it = 0; it < 2; it++) {
                int idx = tid + it * 256;
                int row = idx >> 2, q = idx & 3;
                int k = kc + q * 4;
                float4 v = make_float4(0.f, 0.f, 0.f, 0.f);
                if (kc < K1p) {
                    if (k + 4 <= K1) {
                        v = *(const float4*)(A1 + (long)(m0 + row) * lda1 + aoff + k);
                    } else if (k < K1) {
                        const float* s = A1 + (long)(m0 + row) * lda1 + aoff + k;
                        v.x = s[0];
                        if (k + 1 < K1) v.y = s[1];
                        if (k + 2 < K1) v.z = s[2];
                    }
                } else if (t > 0) {
                    v = *(const float4*)(hprev + (long)(m0 + row) * Hn + (k - K1p));
                }
                if (it) pf1 = v; else pf0 = v;
            }
        };
        auto commit = [&](float* buf) {
            #pragma unroll
            for (int it = 0; it < 2; it++) {
                int idx = tid + it * 256;
                int row = idx >> 2, q = idx & 3;
                float4 v = it ? pf1 : pf0;
                float* d = buf + (q * 4) * PITCH + row;
                d[0] = v.x; d[PITCH] = v.y; d[2 * PITCH] = v.z; d[3 * PITCH] = v.w;
            }
        };

        issue(0);
        commit(sA0);
        __syncthreads();
        for (int c = 0; c < nch; c++) {
            float* cur = (c & 1) ? sA1 : sA0;
            float* nxt = (c & 1) ? sA0 : sA1;
            bool more = (c + 1) < nch;
            if (more) issue((c + 1) << 4);
            const float* swb = sW + (long)(c << 4) * 128 + hu * 8;
            const float* sab = cur + mg8;
            #pragma unroll
            for (int kk = 0; kk < 16; kk++) {
                ulonglong2 wa  = *(const ulonglong2*)(swb + kk * 128);       // (i,i),(f,f)
                ulonglong2 wb2 = *(const ulonglong2*)(swb + kk * 128 + 4);   // (g,g),(o,o)
                ulonglong2 a01 = *(const ulonglong2*)(sab + kk * PITCH);
                ulonglong2 a23 = *(const ulonglong2*)(sab + kk * PITCH + 4);
                fmax2(accI[0], a01.x, wa.x);  fmax2(accI[1], a01.y, wa.x);
                fmax2(accI[2], a23.x, wa.x);  fmax2(accI[3], a23.y, wa.x);
                fmax2(accF[0], a01.x, wa.y);  fmax2(accF[1], a01.y, wa.y);
                fmax2(accF[2], a23.x, wa.y);  fmax2(accF[3], a23.y, wa.y);
                fmax2(accG[0], a01.x, wb2.x); fmax2(accG[1], a01.y, wb2.x);
                fmax2(accG[2], a23.x, wb2.x); fmax2(accG[3], a23.y, wb2.x);
                fmax2(accO[0], a01.x, wb2.y); fmax2(accO[1], a01.y, wb2.y);
                fmax2(accO[2], a23.x, wb2.y); fmax2(accO[3], a23.y, wb2.y);
            }
            if (more) commit(nxt);
            __syncthreads();
        }

        // ---- LSTM cell epilogue ----
        float* hout = ysOut + (long)t * BH;
        bool last = (t == Sn - 1);
        #pragma unroll
        for (int p = 0; p < 4; p++) {
            float2 vi = upk(accI[p]), vf = upk(accF[p]);
            float2 vg = upk(accG[p]), vo = upk(accO[p]);
            #pragma unroll
            for (int h2 = 0; h2 < 2; h2++) {
                int r = m0 + mg8 + 2 * p + h2;
                float gi = h2 ? vi.y : vi.x;
                float gf = h2 ? vf.y : vf.x;
                float gg = h2 ? vg.y : vg.x;
                float go = h2 ? vo.y : vo.x;
                float cc = creg[2 * p + h2];
                float cn = sigf(gf) * cc + sigf(gi) * tanh_f(gg);
                float hh = sigf(go) * tanh_f(cn);
                creg[2 * p + h2] = cn;
                long gi2 = (long)r * Hn + j;
                hout[gi2] = hh;
                if (last) { hFinal[gi2] = hh; cFinal[gi2] = cn; }
            }
        }
        mt_barrier(mt, &s_sense);
    }
}

// ---------------------------------------------------------------------------
// Persistent decoder kernel: T steps x 4 layers (weights streamed from L2)
// + fused FC. c for all 4 layers in registers.
// ---------------------------------------------------------------------------
__global__ __launch_bounds__(256, 1) void dec_kernel(
    const float* __restrict__ x,
    const float* __restrict__ wpk,
    const float* __restrict__ dec_b,
    const float* __restrict__ encC,
    float* __restrict__ decH,             // [2][L][B][H]
    float* __restrict__ outbuf,           // [2][B][IN]
    const float* __restrict__ fcW, const float* __restrict__ fcb,
    float* __restrict__ dout)             // [B][T][IN]
{
    __shared__ __align__(16) float sW[2][16 * 128];
    __shared__ __align__(16) float sA[2][16 * PITCH];
    __shared__ unsigned s_sense;

    int tid = threadIdx.x;
    int bx  = blockIdx.x;
    int mt = bx >> 3, jb = bx & 7;
    int m0 = mt * 128;
    int hu = tid & 15, mg = tid >> 4;
    int mg8 = mg * 8;
    int j = jb * 16 + hu;

    if (tid == 0) s_sense = *(volatile unsigned*)&g_bars[mt];
    __syncthreads();

    // load initial c (encoder final) into registers
    float creg[Ln][8];
    #pragma unroll
    for (int l = 0; l < Ln; l++)
        #pragma unroll
        for (int e = 0; e < 8; e++)
            creg[l][e] = encC[(long)l * BH + (long)(m0 + mg8 + e) * Hn + j];

    for (int t = 0; t < Tn; t++) {
        int cur = t & 1, prv = cur ^ 1;
        for (int l = 0; l < Ln; l++) {
            int K1  = l ? 128 : INn;
            int K1p = l ? 128 : 48;
            int Ktp = K1p + 128;
            int nch = Ktp >> 4;
            const float* W1 = (l == 0)
                ? (wpk + OFF_DIH0 + (long)jb * INn * 128)
                : (wpk + OFF_DIHR + (long)(l - 1) * PK_128 + (long)jb * 128 * 128);
            const float* W2 = wpk + OFF_DHH + (long)l * PK_128 + (long)jb * 128 * 128;
            const float* A1; long lda1, aoff;
            if (l == 0) {
                if (t == 0) { A1 = x; lda1 = (long)Sn * INn; aoff = (long)(Sn - 1) * INn; }
                else        { A1 = outbuf + (long)prv * Bn * INn; lda1 = INn; aoff = 0; }
            } else {
                A1 = decH + ((long)cur * Ln + (l - 1)) * BH; lda1 = Hn; aoff = 0;
            }
            const float* hprev = decH + ((long)prv * Ln + l) * BH;
            const float* bias = dec_b + l * 512;

            float bi = bias[j], bf = bias[128 + j], bg = bias[256 + j], bo = bias[384 + j];
            ull accI[4], accF[4], accG[4], accO[4];
            #pragma unroll
            for (int p = 0; p < 4; p++) {
                accI[p] = pk2(bi, bi); accF[p] = pk2(bf, bf);
                accG[p] = pk2(bg, bg); accO[p] = pk2(bo, bo);
            }

            float4 pa0, pa1, pw0, pw1;
            auto issue = [&](int kc) {
                #pragma unroll
                for (int it = 0; it < 2; it++) {   // A
                    int idx = tid + it * 256;
                    int row = idx >> 2, q = idx & 3;
                    int k = kc + q * 4;
                    float4 v = make_float4(0.f, 0.f, 0.f, 0.f);
                    if (kc < K1p) {
                        if (k + 4 <= K1) {
                            v = *(const float4*)(A1 + (long)(m0 + row) * lda1 + aoff + k);
                        } else if (k < K1) {
                            const float* s = A1 + (long)(m0 + row) * lda1 + aoff + k;
                            v.x = s[0];
                            if (k + 1 < K1) v.y = s[1];
                            if (k + 2 < K1) v.z = s[2];
                        }
                    } else {
                        v = *(const float4*)(hprev + (long)(m0 + row) * Hn + (k - K1p));
                    }
                    if (it) pa1 = v; else pa0 = v;
                }
                #pragma unroll
                for (int it = 0; it < 2; it++) {   // W
                    int idx = tid + it * 256;
                    int kk = idx >> 5, c4 = idx & 31;
                    int k = kc + kk;
                    float4 v = make_float4(0.f, 0.f, 0.f, 0.f);
                    if (k < K1)       v = *(const float4*)(W1 + (long)k * 128 + c4 * 4);
                    else if (k >= K1p) v = *(const float4*)(W2 + (long)(k - K1p) * 128 + c4 * 4);
                    if (it) pw1 = v; else pw0 = v;
                }
            };
            auto commit = [&](int b) {
                #pragma unroll
                for (int it = 0; it < 2; it++) {
                    int idx = tid + it * 256;
                    int row = idx >> 2, q = idx & 3;
                    float4 v = it ? pa1 : pa0;
                    float* d = sA[b] + (q * 4) * PITCH + row;
                    d[0] = v.x; d[PITCH] = v.y; d[2 * PITCH] = v.z; d[3 * PITCH] = v.w;
                }
                #pragma unroll
                for (int it = 0; it < 2; it++) {
                    int idx = tid + it * 256;
                    int kk = idx >> 5, c4 = idx & 31;
                    *(float4*)(sW[b] + kk * 128 + c4 * 4) = it ? pw1 : pw0;
                }
            };

            issue(0);
            commit(0);
            __syncthreads();
            for (int c = 0; c < nch; c++) {
                int cb = c & 1;
                bool more = (c + 1) < nch;
                if (more) issue((c + 1) << 4);
                const float* swb = sW[cb] + hu * 8;
                const float* sab = sA[cb] + mg8;
                #pragma unroll
                for (int kk = 0; kk < 16; kk++) {
                    ulonglong2 wa  = *(const ulonglong2*)(swb + kk * 128);
                    ulonglong2 wb2 = *(const ulonglong2*)(swb + kk * 128 + 4);
                    ulonglong2 a01 = *(const ulonglong2*)(sab + kk * PITCH);
                    ulonglong2 a23 = *(const ulonglong2*)(sab + kk * PITCH + 4);
                    fmax2(accI[0], a01.x, wa.x);  fmax2(accI[1], a01.y, wa.x);
                    fmax2(accI[2], a23.x, wa.x);  fmax2(accI[3], a23.y, wa.x);
                    fmax2(accF[0], a01.x, wa.y);  fmax2(accF[1], a01.y, wa.y);
                    fmax2(accF[2], a23.x, wa.y);  fmax2(accF[3], a23.y, wa.y);
                    fmax2(accG[0], a01.x, wb2.x); fmax2(accG[1], a01.y, wb2.x);
                    fmax2(accG[2], a23.x, wb2.x); fmax2(accG[3], a23.y, wb2.x);
                    fmax2(accO[0], a01.x, wb2.y); fmax2(accO[1], a01.y, wb2.y);
                    fmax2(accO[2], a23.x, wb2.y); fmax2(accO[3], a23.y, wb2.y);
                }
                if (more) commit(cb ^ 1);
                __syncthreads();
            }

            // epilogue
            float* hout = decH + ((long)cur * Ln + l) * BH;
            #pragma unroll
            for (int p = 0; p < 4; p++) {
                float2 vi = upk(accI[p]), vf = upk(accF[p]);
                float2 vg = upk(accG[p]), vo = upk(accO[p]);
                #pragma unroll
                for (int h2 = 0; h2 < 2; h2++) {
                    int r = m0 + mg8 + 2 * p + h2;
                    float gi = h2 ? vi.y : vi.x;
                    float gf = h2 ? vf.y : vf.x;
                    float gg = h2 ? vg.y : vg.x;
                    float go = h2 ? vo.y : vo.x;
                    float cc = creg[l][2 * p + h2];
                    float cn = sigf(gf) * cc + sigf(gi) * tanh_f(gg);
                    float hh = sigf(go) * tanh_f(cn);
                    creg[l][2 * p + h2] = cn;
                    hout[(long)r * Hn + j] = hh;
                }
            }
            mt_barrier(mt, &s_sense);
        }

        // ---- FC: rows of this mt, cols split over jb ----
        {
            const float* h3 = decH + ((long)cur * Ln + 3) * BH;
            float* oc = outbuf + (long)cur * Bn * INn;
            int i0 = jb * 6;
            int nc2 = INn - i0; if (nc2 > 6) nc2 = 6;
            for (int idx = tid; idx < 128 * nc2; idx += 256) {
                int r = idx / nc2, ii = idx - r * nc2;
                int i = i0 + ii;
                const float4* hr = (const float4*)(h3 + (long)(m0 + r) * Hn);
                const float4* wr = (const float4*)(fcW + (long)i * Hn);
                float acc = fcb[i];
                #pragma unroll
                for (int k = 0; k < 32; k++) {
                    float4 a = hr[k], b = wr[k];
                    acc = fmaf(a.x, b.x, acc); acc = fmaf(a.y, b.y, acc);
                    acc = fmaf(a.z, b.z, acc); acc = fmaf(a.w, b.w, acc);
                }
                int m = m0 + r;
                oc[(long)m * INn + i] = acc;
                dout[(long)m * Tn * INn + (long)t * INn + i] = acc;
            }
            mt_barrier(mt, &s_sense);
        }
    }
}

// ---------------------------------------------------------------------------
// Host orchestration: 16 pack nodes + 4 encoder + 1 decoder = 21 graph nodes.
// No memset/memcpy nodes; all state handled inside kernels.
// ---------------------------------------------------------------------------
extern "C" void kernel_launch(void* const* d_in, const int* in_sizes, int n_in,
                              void* d_out, int out_size)
{
    const float* x        = (const float*)d_in[0];
    const float* enc_Wih0 = (const float*)d_in[2];
    const float* enc_WihR = (const float*)d_in[3];
    const float* enc_Whh  = (const float*)d_in[4];
    const float* enc_b    = (const float*)d_in[5];
    const float* dec_Wih0 = (const float*)d_in[6];
    const float* dec_WihR = (const float*)d_in[7];
    const float* dec_Whh  = (const float*)d_in[8];
    const float* dec_b    = (const float*)d_in[9];
    const float* fc_W     = (const float*)d_in[10];
    const float* fc_b     = (const float*)d_in[11];
    float* out = (float*)d_out;

    float *ysA, *ysB, *encC, *decH, *outb, *wpk;
    cudaGetSymbolAddress((void**)&ysA,  g_ysA);
    cudaGetSymbolAddress((void**)&ysB,  g_ysB);
    cudaGetSymbolAddress((void**)&encC, g_encC);
    cudaGetSymbolAddress((void**)&decH, g_decH);
    cudaGetSymbolAddress((void**)&outb, g_out2);
    cudaGetSymbolAddress((void**)&wpk,  g_wpk);

    size_t smem0 = (size_t)(176 * 128 + 2 * 16 * PITCH) * 4;   // l0: 98.9 KB
    size_t smemR = (size_t)(256 * 128 + 2 * 16 * PITCH) * 4;   // l>=1: 147.9 KB
    cudaFuncSetAttribute(enc_layer_kernel,
                         cudaFuncAttributeMaxDynamicSharedMemorySize, (int)smemR);

    auto pack = [&](const float* W, long off, int K) {
        int total = 8 * K * 128;
        pack_w_kernel<<<(total + 255) / 256, 256>>>(W, wpk + off, K);
    };
    pack(enc_Wih0, OFF_EIH0, INn);
    for (int l = 1; l < Ln; l++) pack(enc_WihR + (long)(l - 1) * 512 * 128, OFF_EIHR + (l - 1) * PK_128, 128);
    for (int l = 0; l < Ln; l++) pack(enc_Whh  + (long)l * 512 * 128,       OFF_EHH  + l * PK_128,       128);
    pack(dec_Wih0, OFF_DIH0, INn);
    for (int l = 1; l < Ln; l++) pack(dec_WihR + (long)(l - 1) * 512 * 128, OFF_DIHR + (l - 1) * PK_128, 128);
    for (int l = 0; l < Ln; l++) pack(dec_Whh  + (long)l * 512 * 128,       OFF_DHH  + l * PK_128,       128);

    // ---- encoder: 4 persistent layer kernels ----
    enc_layer_kernel<<<128, 256, smem0>>>(
        x, (long)Sn * INn, (long)INn, INn, 48,
        wpk + OFF_EIH0, wpk + OFF_EHH, enc_b,
        ysA, decH + (long)(Ln + 0) * BH, encC);

    float* yin = ysA; float* yout = ysB;
    for (int l = 1; l < Ln; l++) {
        enc_layer_kernel<<<128, 256, smemR>>>(
            yin, (long)Hn, BH, 128, 128,
            wpk + OFF_EIHR + (long)(l - 1) * PK_128,
            wpk + OFF_EHH + (long)l * PK_128,
            enc_b + l * 512,
            yout, decH + (long)(Ln + l) * BH, encC + (long)l * BH);
        float* tmp = yin; yin = yout; yout = tmp;
    }

    // ---- decoder: one persistent kernel ----
    dec_kernel<<<128, 256>>>(x, wpk, dec_b, encC, decH, outb, fc_W, fc_b, out);
}

// round 16
// speedup vs baseline: 1.0950x; 1.0950x over previous
#include <cuda_runtime.h>
#include <cuda_bf16.h>
#include <cstdint>

typedef unsigned long long ull;

// ---------------------------------------------------------------------------
// Problem constants
// ---------------------------------------------------------------------------
namespace {
constexpr int Bn  = 2048;
constexpr int Sn  = 200;
constexpr int Tn  = 50;
constexpr int INn = 44;
constexpr int Hn  = 128;
constexpr int Ln  = 4;
constexpr long BH = (long)Bn * Hn;            // 262144 elems per (B,H) slab

// fp32 packed weights (gate-gathered, duplicated) for rec + decoder
constexpr long PK_IH0 = 8L * 44  * 128;
constexpr long PK_128 = 8L * 128 * 128;
constexpr long OFF_EIH0 = 0;
constexpr long OFF_EIHR = OFF_EIH0 + PK_IH0;
constexpr long OFF_EHH  = OFF_EIHR + 3 * PK_128;
constexpr long OFF_DIH0 = OFF_EHH  + 4 * PK_128;
constexpr long OFF_DIHR = OFF_DIH0 + PK_IH0;
constexpr long OFF_DHH  = OFF_DIHR + 3 * PK_128;
constexpr long PK_TOTAL = OFF_DHH  + 4 * PK_128;

constexpr int PITCH = 132;                    // rec sA pitch in floats

// mma B fragment packs: l0 (ktiles=4) then 3 layers (ktiles=8)
// entry layout: u = ((ntg*ktiles + kt)*32 + lane)*2 + reg  (uint32 = bf16x2)
constexpr long BPK0   = 0;                    // l0: 64*4*32*2 = 16384
constexpr long BPKR   = 16384;                // each rest: 64*8*32*2 = 32768
constexpr long BPK_TOTAL = BPKR + 3L * 32768; // 114688

constexpr long MROWS = (long)Sn * Bn;         // 409600 GEMM rows
}

// ---------------------------------------------------------------------------
// Scratch (static device globals; no runtime allocation allowed)
// ---------------------------------------------------------------------------
__device__ float g_ysA[MROWS * Hn];                 // fp32 h history (current layer)
__device__ __nv_bfloat16 g_ysH[MROWS * Hn];         // bf16 hi of h
__device__ __nv_bfloat16 g_ysL[MROWS * Hn];         // bf16 lo
__device__ __nv_bfloat16 g_xH[MROWS * 64];          // x split-bf16, K padded to 64
__device__ __nv_bfloat16 g_xL[MROWS * 64];
__device__ float g_P[MROWS * 512];                  // precomputed input projections
__device__ float g_encC[(long)Ln * Bn * Hn];
__device__ float g_decH[2L * Ln * Bn * Hn];
__device__ float g_out2[2L * Bn * INn];
__device__ float g_wpk[PK_TOTAL];
__device__ uint32_t g_bpkH[BPK_TOTAL];
__device__ uint32_t g_bpkL[BPK_TOTAL];
__device__ unsigned g_barc[16];
__device__ unsigned g_bars[16];

// ---------------------------------------------------------------------------
// f32x2 + math helpers
// ---------------------------------------------------------------------------
__device__ __forceinline__ ull pk2(float x, float y) {
    ull r; asm("mov.b64 %0, {%1, %2};" : "=l"(r) : "f"(x), "f"(y)); return r;
}
__device__ __forceinline__ float2 upk(ull v) {
    float2 r; asm("mov.b64 {%0, %1}, %2;" : "=f"(r.x), "=f"(r.y) : "l"(v)); return r;
}
__device__ __forceinline__ void fmax2(ull& d, ull a, ull b) {
    asm("fma.rn.f32x2 %0, %1, %2, %0;" : "+l"(d) : "l"(a), "l"(b));
}
__device__ __forceinline__ float sigf(float x) {
    return __fdividef(1.f, 1.f + __expf(-x));
}
__device__ __forceinline__ float tanh_f(float x) {
    float xc = fminf(fmaxf(x, -15.f), 15.f);
    float e = __expf(2.f * xc);
    return __fdividef(e - 1.f, e + 1.f);
}

// ---------------------------------------------------------------------------
// mma.sync helpers (classic HMMA path — valid on plain sm_103 target)
// ---------------------------------------------------------------------------
__device__ __forceinline__ uint32_t smem_u32(const void* p) {
    uint32_t a;
    asm("{ .reg .u64 t; cvta.to.shared.u64 t, %1; cvt.u32.u64 %0, t; }"
        : "=r"(a) : "l"(p));
    return a;
}
__device__ __forceinline__ void ldm_x4(uint32_t* r, uint32_t addr) {
    asm volatile("ldmatrix.sync.aligned.m8n8.x4.shared.b16 {%0,%1,%2,%3}, [%4];"
        : "=r"(r[0]), "=r"(r[1]), "=r"(r[2]), "=r"(r[3]) : "r"(addr));
}
__device__ __forceinline__ void mma_bf16(float* c, const uint32_t* a,
                                         uint32_t b0, uint32_t b1) {
    asm volatile(
        "mma.sync.aligned.m16n8k16.row.col.f32.bf16.bf16.f32 "
        "{%0,%1,%2,%3}, {%4,%5,%6,%7}, {%8,%9}, {%0,%1,%2,%3};"
        : "+f"(c[0]), "+f"(c[1]), "+f"(c[2]), "+f"(c[3])
        : "r"(a[0]), "r"(a[1]), "r"(a[2]), "r"(a[3]), "r"(b0), "r"(b1));
}
__device__ __forceinline__ uint32_t pack_bf16x2(__nv_bfloat16 lo, __nv_bfloat16 hi) {
    return ((uint32_t)__bfloat16_as_ushort(hi) << 16) |
           (uint32_t)__bfloat16_as_ushort(lo);
}

// ---------------------------------------------------------------------------
// prepA: pack all fp32 weight matrices (gate-gathered dup layout) -> g_wpk
// ---------------------------------------------------------------------------
__global__ void prepA_kernel(const float* __restrict__ eW0, const float* __restrict__ eWR,
                             const float* __restrict__ eHH, const float* __restrict__ dW0,
                             const float* __restrict__ dWR, const float* __restrict__ dHH,
                             float* __restrict__ wpk)
{
    int seg = blockIdx.y;
    const float* W; long off; int K;
    if (seg == 0)      { W = eW0;                               off = OFF_EIH0;                      K = INn; }
    else if (seg < 4)  { W = eWR + (long)(seg - 1) * 512 * 128;  off = OFF_EIHR + (seg - 1) * PK_128; K = 128; }
    else if (seg < 8)  { W = eHH + (long)(seg - 4) * 512 * 128;  off = OFF_EHH  + (seg - 4) * PK_128; K = 128; }
    else if (seg == 8) { W = dW0;                               off = OFF_DIH0;                      K = INn; }
    else if (seg < 12) { W = dWR + (long)(seg - 9) * 512 * 128;  off = OFF_DIHR + (seg - 9) * PK_128; K = 128; }
    else               { W = dHH + (long)(seg - 12) * 512 * 128; off = OFF_DHH + (seg - 12) * PK_128; K = 128; }

    int idx = blockIdx.x * blockDim.x + threadIdx.x;
    int total = 8 * K * 128;
    if (idx >= total) return;
    int inner = idx & 127;
    int rem   = idx >> 7;              // jb*K + k
    int k  = rem % K;
    int jb = rem / K;
    int hu = inner >> 3;
    int ge = (inner >> 1) & 3;
    wpk[off + idx] = W[(long)(ge * 128 + jb * 16 + hu) * K + k];
}

// ---------------------------------------------------------------------------
// prepB: B fragment packs (split bf16) + x split-bf16 conversion.
// B entry decode: u = ((ntg*ktiles + kt)*32 + lane)*2 + r
//   n = ntg*8 + (lane>>2); j = n>>2; g = n&3; W row = g*128+j
//   k0 = kt*16 + (lane&3)*2 + r*8; value pair (k0, k0+1)
// ---------------------------------------------------------------------------
__global__ void prepB_kernel(const float* __restrict__ x,
                             const float* __restrict__ eW0, const float* __restrict__ eWR,
                             uint32_t* __restrict__ bpkH, uint32_t* __restrict__ bpkL,
                             __nv_bfloat16* __restrict__ xH, __nv_bfloat16* __restrict__ xL)
{
    long idx = (long)blockIdx.x * blockDim.x + threadIdx.x;
    const long S0 = 16384;                 // l0 pack entries
    const long SR = 32768;                 // per rest layer
    if (idx < S0 + 3 * SR) {
        const float* W; int Kw, ktiles; long off, u;
        if (idx < S0) { W = eW0; Kw = INn; ktiles = 4; off = BPK0; u = idx; }
        else {
            long r2 = idx - S0;
            int l = (int)(r2 / SR);
            u = r2 - (long)l * SR;
            W = eWR + (long)l * 512 * 128; Kw = 128; ktiles = 8;
            off = BPKR + (long)l * SR;
        }
        int r  = (int)(u & 1);
        long t1 = u >> 1;
        int lane = (int)(t1 & 31);
        long t2 = t1 >> 5;
        int kt = (int)(t2 % ktiles);
        int ntg = (int)(t2 / ktiles);
        int n = ntg * 8 + (lane >> 2);
        int j = n >> 2, g = n & 3;
        int k0 = kt * 16 + (lane & 3) * 2 + r * 8;
        float v0 = (k0     < Kw) ? W[(long)(g * 128 + j) * Kw + k0]     : 0.f;
        float v1 = (k0 + 1 < Kw) ? W[(long)(g * 128 + j) * Kw + k0 + 1] : 0.f;
        __nv_bfloat16 h0 = __float2bfloat16(v0);
        __nv_bfloat16 h1 = __float2bfloat16(v1);
        __nv_bfloat16 l0 = __float2bfloat16(v0 - __bfloat162float(h0));
        __nv_bfloat16 l1 = __float2bfloat16(v1 - __bfloat162float(h1));
        bpkH[off + u] = pack_bf16x2(h0, h1);
        bpkL[off + u] = pack_bf16x2(l0, l1);
        return;
    }
    idx -= S0 + 3 * SR;
    if (idx < MROWS * 64) {
        long row = idx >> 6;
        int k = (int)(idx & 63);
        float v = (k < INn) ? x[row * INn + k] : 0.f;
        __nv_bfloat16 hi = __float2bfloat16(v);
        __nv_bfloat16 lo = __float2bfloat16(v - __bfloat162float(hi));
        xH[idx] = hi;
        xL[idx] = lo;
    }
}

// ---------------------------------------------------------------------------
// Pre-GEMM via mma.sync bf16, split-bf16 3 passes.
// grid.x = 3200 (M tiles of 128), 128 threads (4 warps; warp owns 32 rows).
// A hi/lo staged in smem (skewed pitch), B fragments via LDG from g_bpk*.
// Output P[row][512] fp32.
// ---------------------------------------------------------------------------
__global__ __launch_bounds__(128) void pre_gemm_kernel(
    const __nv_bfloat16* __restrict__ AH,
    const __nv_bfloat16* __restrict__ AL,
    const uint32_t* __restrict__ BpkH,
    const uint32_t* __restrict__ BpkL,
    float* __restrict__ P, int Kp, int ktiles, int l0map)
{
    extern __shared__ __align__(16) char smemc[];
    const int pitchB = (Kp + 8) * 2;              // bytes per smem row
    char* sAH = smemc;
    char* sAL = smemc + (long)128 * pitchB;

    int tid = threadIdx.x;
    int lane = tid & 31, w = tid >> 5;
    int gid = lane >> 2, tig = lane & 3;
    long tile = blockIdx.x;
    int mbase = w * 32;

    // stage A hi/lo: 128 rows x Kp bf16 each
    {
        int cpr = Kp >> 3;                        // 16B chunks per row
        int tot = 128 * cpr;
        for (int i = tid; i < tot; i += 128) {
            int row = i / cpr, c = i - row * cpr;
            long src = (tile * 128 + row) * (long)Kp + c * 8;
            *(uint4*)(sAH + (long)row * pitchB + c * 16) = *(const uint4*)(AH + src);
            *(uint4*)(sAL + (long)row * pitchB + c * 16) = *(const uint4*)(AL + src);
        }
    }
    __syncthreads();

    uint32_t sbH = smem_u32(sAH), sbL = smem_u32(sAL);

    // output rows for this thread (c0,c1 -> row gid; c2,c3 -> row gid+8)
    long prow[2][2];
    #pragma unroll
    for (int mt = 0; mt < 2; mt++) {
        long G0 = tile * 128 + mbase + mt * 16 + gid;
        long G1 = G0 + 8;
        if (l0map) {
            prow[mt][0] = (G0 % Sn) * Bn + G0 / Sn;
            prow[mt][1] = (G1 % Sn) * Bn + G1 / Sn;
        } else {
            prow[mt][0] = G0; prow[mt][1] = G1;
        }
    }

    // ldmatrix lane address components
    int q = lane >> 3, rr = lane & 7;
    int lrow = ((q & 1) << 3) + rr;
    int lcol = (q >> 1) << 3;

    for (int nc = 0; nc < 8; nc++) {
        float cacc[2][8][4];
        #pragma unroll
        for (int mt = 0; mt < 2; mt++)
            #pragma unroll
            for (int nt = 0; nt < 8; nt++)
                #pragma unroll
                for (int e = 0; e < 4; e++) cacc[mt][nt][e] = 0.f;

        for (int kt = 0; kt < ktiles; kt++) {
            uint32_t bH[8][2], bL[8][2];
            #pragma unroll
            for (int nt = 0; nt < 8; nt++) {
                long bi = (((long)(nc * 8 + nt) * ktiles + kt) * 32 + lane) * 2;
                bH[nt][0] = BpkH[bi];     bH[nt][1] = BpkH[bi + 1];
                bL[nt][0] = BpkL[bi];     bL[nt][1] = BpkL[bi + 1];
            }
            #pragma unroll
            for (int mt = 0; mt < 2; mt++) {
                uint32_t aH[4], aL[4];
                uint32_t aoff = (uint32_t)(mbase + mt * 16 + lrow) * pitchB
                              + (uint32_t)(kt * 16 + lcol) * 2;
                ldm_x4(aH, sbH + aoff);
                ldm_x4(aL, sbL + aoff);
                #pragma unroll
                for (int nt = 0; nt < 8; nt++) {
                    mma_bf16(cacc[mt][nt], aH, bH[nt][0], bH[nt][1]);
                    mma_bf16(cacc[mt][nt], aH, bL[nt][0], bL[nt][1]);
                    mma_bf16(cacc[mt][nt], aL, bH[nt][0], bH[nt][1]);
                }
            }
        }

        #pragma unroll
        for (int mt = 0; mt < 2; mt++)
            #pragma unroll
            for (int nt = 0; nt < 8; nt++) {
                int col = nc * 64 + nt * 8 + tig * 2;
                *(float2*)(P + prow[mt][0] * 512 + col) =
                    make_float2(cacc[mt][nt][0], cacc[mt][nt][1]);
                *(float2*)(P + prow[mt][1] * 512 + col) =
                    make_float2(cacc[mt][nt][2], cacc[mt][nt][3]);
            }
    }
}

// ---------------------------------------------------------------------------
// mt-local barrier (8 CTAs sharing a batch-row tile)
// ---------------------------------------------------------------------------
__device__ __forceinline__ void mt_barrier(int mt, unsigned* s_sense) {
    __threadfence();
    __syncthreads();
    if (threadIdx.x == 0) {
        unsigned ns = *s_sense ^ 1u;
        *s_sense = ns;
        unsigned a = atomicAdd(&g_barc[mt], 1u);
        if (a == 7u) {
            g_barc[mt] = 0u;
            __threadfence();
            atomicExch(&g_bars[mt], ns);
        } else {
            volatile unsigned* p = &g_bars[mt];
            while (*p != ns) __nanosleep(64);
            __threadfence();
        }
    }
    __syncthreads();
}

// ---------------------------------------------------------------------------
// Recurrent kernel (encoder): gates = P[t] + h_{t-1} @ Whh^T + b.
// grid = 128 CTAs (16 mt x 8 jb), 256 threads. Whh resident in smem.
// ---------------------------------------------------------------------------
__global__ __launch_bounds__(256, 1) void rec_kernel(
    const float* __restrict__ P,
    const float* __restrict__ WpkHH,
    const float* __restrict__ bias,
    float* __restrict__ ysOut,
    __nv_bfloat16* __restrict__ ysH, __nv_bfloat16* __restrict__ ysL,  // may be null
    float* __restrict__ hFinal, float* __restrict__ cFinal)
{
    extern __shared__ float sm[];
    float* sW = sm;                         // 128 x 128
    float* sA = sm + 128 * 128;             // [k][row], pitch PITCH
    __shared__ unsigned s_sense;

    int tid = threadIdx.x;
    int bx = blockIdx.x;
    int mt = bx >> 3, jb = bx & 7;
    int m0 = mt * 128;
    int hu = tid & 15, mg = tid >> 4;
    int mg8 = mg * 8;
    int j = jb * 16 + hu;

    if (tid == 0) s_sense = *(volatile unsigned*)&g_bars[mt];

    {   // resident weights
        const float4* wsrc = (const float4*)(WpkHH + (long)jb * 128 * 128);
        for (int i = tid; i < 128 * 32; i += 256) ((float4*)sW)[i] = wsrc[i];
    }
    __syncthreads();

    float bi = bias[j], bf = bias[128 + j], bg = bias[256 + j], bo = bias[384 + j];
    float creg[8];
    #pragma unroll
    for (int i = 0; i < 8; i++) creg[i] = 0.f;

    const float* swb = sW + hu * 8;
    const float* sab = sA + mg8;

    for (int t = 0; t < Sn; t++) {
        float4 p4[8];
        {
            const float* Pt = P + ((long)t * Bn + m0 + mg8) * 512 + j * 4;
            #pragma unroll
            for (int e = 0; e < 8; e++) p4[e] = *(const float4*)(Pt + (long)e * 512);
        }
        if (t > 0) {
            const float* hprev = ysOut + (long)(t - 1) * BH;
            for (int c = tid; c < 4096; c += 256) {
                int row = c >> 5, k4 = c & 31;
                float4 v = *(const float4*)(hprev + (long)(m0 + row) * Hn + k4 * 4);
                float* d = sA + (k4 * 4) * PITCH + row;
                d[0] = v.x; d[PITCH] = v.y; d[2 * PITCH] = v.z; d[3 * PITCH] = v.w;
            }
            __syncthreads();
        }

        ull accI[4], accF[4], accG[4], accO[4];
        #pragma unroll
        for (int p = 0; p < 4; p++) {
            accI[p] = pk2(bi + p4[2 * p].x, bi + p4[2 * p + 1].x);
            accF[p] = pk2(bf + p4[2 * p].y, bf + p4[2 * p + 1].y);
            accG[p] = pk2(bg + p4[2 * p].z, bg + p4[2 * p + 1].z);
            accO[p] = pk2(bo + p4[2 * p].w, bo + p4[2 * p + 1].w);
        }

        if (t > 0) {
            for (int kc = 0; kc < 128; kc += 16) {
                #pragma unroll
                for (int k2 = 0; k2 < 16; k2++) {
                    int kk = kc + k2;
                    ulonglong2 wa  = *(const ulonglong2*)(swb + (long)kk * 128);
                    ulonglong2 wb2 = *(const ulonglong2*)(swb + (long)kk * 128 + 4);
                    ulonglong2 a01 = *(const ulonglong2*)(sab + (long)kk * PITCH);
                    ulonglong2 a23 = *(const ulonglong2*)(sab + (long)kk * PITCH + 4);
                    fmax2(accI[0], a01.x, wa.x);  fmax2(accI[1], a01.y, wa.x);
                    fmax2(accI[2], a23.x, wa.x);  fmax2(accI[3], a23.y, wa.x);
                    fmax2(accF[0], a01.x, wa.y);  fmax2(accF[1], a01.y, wa.y);
                    fmax2(accF[2], a23.x, wa.y);  fmax2(accF[3], a23.y, wa.y);
                    fmax2(accG[0], a01.x, wb2.x); fmax2(accG[1], a01.y, wb2.x);
                    fmax2(accG[2], a23.x, wb2.x); fmax2(accG[3], a23.y, wb2.x);
                    fmax2(accO[0], a01.x, wb2.y); fmax2(accO[1], a01.y, wb2.y);
                    fmax2(accO[2], a23.x, wb2.y); fmax2(accO[3], a23.y, wb2.y);
                }
            }
        }

        float* hout = ysOut + (long)t * BH;
        bool last = (t == Sn - 1);
        #pragma unroll
        for (int p = 0; p < 4; p++) {
            float2 vi = upk(accI[p]), vf = upk(accF[p]);
            float2 vg = upk(accG[p]), vo = upk(accO[p]);
            #pragma unroll
            for (int h2 = 0; h2 < 2; h2++) {
                int r = m0 + mg8 + 2 * p + h2;
                float gi = h2 ? vi.y : vi.x;
                float gf = h2 ? vf.y : vf.x;
                float gg = h2 ? vg.y : vg.x;
                float go = h2 ? vo.y : vo.x;
                float cc = creg[2 * p + h2];
                float cn = sigf(gf) * cc + sigf(gi) * tanh_f(gg);
                float hh = sigf(go) * tanh_f(cn);
                creg[2 * p + h2] = cn;
                long gi2 = (long)r * Hn + j;
                hout[gi2] = hh;
                if (ysH) {
                    __nv_bfloat16 hib = __float2bfloat16(hh);
                    __nv_bfloat16 lob = __float2bfloat16(hh - __bfloat162float(hib));
                    ysH[(long)t * BH + gi2] = hib;
                    ysL[(long)t * BH + gi2] = lob;
                }
                if (last) { hFinal[gi2] = hh; cFinal[gi2] = cn; }
            }
        }
        mt_barrier(mt, &s_sense);
    }
}

// ---------------------------------------------------------------------------
// Persistent decoder kernel (proven in R10): T steps x 4 layers + FC.
// ---------------------------------------------------------------------------
__global__ __launch_bounds__(256, 1) void dec_kernel(
    const float* __restrict__ x,
    const float* __restrict__ wpk,
    const float* __restrict__ dec_b,
    const float* __restrict__ encC,
    float* __restrict__ decH,
    float* __restrict__ outbuf,
    const float* __restrict__ fcW, const float* __restrict__ fcb,
    float* __restrict__ dout)
{
    __shared__ __align__(16) float sW[2][16 * 128];
    __shared__ __align__(16) float sA[2][16 * PITCH];
    __shared__ unsigned s_sense;

    int tid = threadIdx.x;
    int bx  = blockIdx.x;
    int mt = bx >> 3, jb = bx & 7;
    int m0 = mt * 128;
    int hu = tid & 15, mg = tid >> 4;
    int mg8 = mg * 8;
    int j = jb * 16 + hu;

    if (tid == 0) s_sense = *(volatile unsigned*)&g_bars[mt];
    __syncthreads();

    float creg[Ln][8];
    #pragma unroll
    for (int l = 0; l < Ln; l++)
        #pragma unroll
        for (int e = 0; e < 8; e++)
            creg[l][e] = encC[(long)l * BH + (long)(m0 + mg8 + e) * Hn + j];

    for (int t = 0; t < Tn; t++) {
        int cur = t & 1, prv = cur ^ 1;
        for (int l = 0; l < Ln; l++) {
            int K1  = l ? 128 : INn;
            int K1p = l ? 128 : 48;
            int Ktp = K1p + 128;
            int nch = Ktp >> 4;
            const float* W1 = (l == 0)
                ? (wpk + OFF_DIH0 + (long)jb * INn * 128)
                : (wpk + OFF_DIHR + (long)(l - 1) * PK_128 + (long)jb * 128 * 128);
            const float* W2 = wpk + OFF_DHH + (long)l * PK_128 + (long)jb * 128 * 128;
            const float* A1; long lda1, aoff;
            if (l == 0) {
                if (t == 0) { A1 = x; lda1 = (long)Sn * INn; aoff = (long)(Sn - 1) * INn; }
                else        { A1 = outbuf + (long)prv * Bn * INn; lda1 = INn; aoff = 0; }
            } else {
                A1 = decH + ((long)cur * Ln + (l - 1)) * BH; lda1 = Hn; aoff = 0;
            }
            const float* hprev = decH + ((long)prv * Ln + l) * BH;
            const float* bias = dec_b + l * 512;

            float bi = bias[j], bf = bias[128 + j], bg = bias[256 + j], bo = bias[384 + j];
            ull accI[4], accF[4], accG[4], accO[4];
            #pragma unroll
            for (int p = 0; p < 4; p++) {
                accI[p] = pk2(bi, bi); accF[p] = pk2(bf, bf);
                accG[p] = pk2(bg, bg); accO[p] = pk2(bo, bo);
            }

            float4 pa0, pa1, pw0, pw1;
            auto issue = [&](int kc) {
                #pragma unroll
                for (int it = 0; it < 2; it++) {
                    int idx = tid + it * 256;
                    int row = idx >> 2, q = idx & 3;
                    int k = kc + q * 4;
                    float4 v = make_float4(0.f, 0.f, 0.f, 0.f);
                    if (kc < K1p) {
                        if (k + 4 <= K1) {
                            v = *(const float4*)(A1 + (long)(m0 + row) * lda1 + aoff + k);
                        } else if (k < K1) {
                            const float* s = A1 + (long)(m0 + row) * lda1 + aoff + k;
                            v.x = s[0];
                            if (k + 1 < K1) v.y = s[1];
                            if (k + 2 < K1) v.z = s[2];
                        }
                    } else {
                        v = *(const float4*)(hprev + (long)(m0 + row) * Hn + (k - K1p));
                    }
                    if (it) pa1 = v; else pa0 = v;
                }
                #pragma unroll
                for (int it = 0; it < 2; it++) {
                    int idx = tid + it * 256;
                    int kk = idx >> 5, c4 = idx & 31;
                    int k = kc + kk;
                    float4 v = make_float4(0.f, 0.f, 0.f, 0.f);
                    if (k < K1)        v = *(const float4*)(W1 + (long)k * 128 + c4 * 4);
                    else if (k >= K1p) v = *(const float4*)(W2 + (long)(k - K1p) * 128 + c4 * 4);
                    if (it) pw1 = v; else pw0 = v;
                }
            };
            auto commit = [&](int b) {
                #pragma unroll
                for (int it = 0; it < 2; it++) {
                    int idx = tid + it * 256;
                    int row = idx >> 2, q = idx & 3;
                    float4 v = it ? pa1 : pa0;
                    float* d = sA[b] + (q * 4) * PITCH + row;
                    d[0] = v.x; d[PITCH] = v.y; d[2 * PITCH] = v.z; d[3 * PITCH] = v.w;
                }
                #pragma unroll
                for (int it = 0; it < 2; it++) {
                    int idx = tid + it * 256;
                    int kk = idx >> 5, c4 = idx & 31;
                    *(float4*)(sW[b] + kk * 128 + c4 * 4) = it ? pw1 : pw0;
                }
            };

            issue(0);
            commit(0);
            __syncthreads();
            for (int c = 0; c < nch; c++) {
                int cb = c & 1;
                bool more = (c + 1) < nch;
                if (more) issue((c + 1) << 4);
                const float* swb = sW[cb] + hu * 8;
                const float* sab = sA[cb] + mg8;
                #pragma unroll
                for (int kk = 0; kk < 16; kk++) {
                    ulonglong2 wa  = *(const ulonglong2*)(swb + kk * 128);
                    ulonglong2 wb2 = *(const ulonglong2*)(swb + kk * 128 + 4);
                    ulonglong2 a01 = *(const ulonglong2*)(sab + kk * PITCH);
                    ulonglong2 a23 = *(const ulonglong2*)(sab + kk * PITCH + 4);
                    fmax2(accI[0], a01.x, wa.x);  fmax2(accI[1], a01.y, wa.x);
                    fmax2(accI[2], a23.x, wa.x);  fmax2(accI[3], a23.y, wa.x);
                    fmax2(accF[0], a01.x, wa.y);  fmax2(accF[1], a01.y, wa.y);
                    fmax2(accF[2], a23.x, wa.y);  fmax2(accF[3], a23.y, wa.y);
                    fmax2(accG[0], a01.x, wb2.x); fmax2(accG[1], a01.y, wb2.x);
                    fmax2(accG[2], a23.x, wb2.x); fmax2(accG[3], a23.y, wb2.x);
                    fmax2(accO[0], a01.x, wb2.y); fmax2(accO[1], a01.y, wb2.y);
                    fmax2(accO[2], a23.x, wb2.y); fmax2(accO[3], a23.y, wb2.y);
                }
                if (more) commit(cb ^ 1);
                __syncthreads();
            }

            float* hout = decH + ((long)cur * Ln + l) * BH;
            #pragma unroll
            for (int p = 0; p < 4; p++) {
                float2 vi = upk(accI[p]), vf = upk(accF[p]);
                float2 vg = upk(accG[p]), vo = upk(accO[p]);
                #pragma unroll
                for (int h2 = 0; h2 < 2; h2++) {
                    int r = m0 + mg8 + 2 * p + h2;
                    float gi = h2 ? vi.y : vi.x;
                    float gf = h2 ? vf.y : vf.x;
                    float gg = h2 ? vg.y : vg.x;
                    float go = h2 ? vo.y : vo.x;
                    float cc = creg[l][2 * p + h2];
                    float cn = sigf(gf) * cc + sigf(gi) * tanh_f(gg);
                    float hh = sigf(go) * tanh_f(cn);
                    creg[l][2 * p + h2] = cn;
                    hout[(long)r * Hn + j] = hh;
                }
            }
            mt_barrier(mt, &s_sense);
        }

        {
            const float* h3 = decH + ((long)cur * Ln + 3) * BH;
            float* oc = outbuf + (long)cur * Bn * INn;
            int i0 = jb * 6;
            int nc2 = INn - i0; if (nc2 > 6) nc2 = 6;
            for (int idx = tid; idx < 128 * nc2; idx += 256) {
                int r = idx / nc2, ii = idx - r * nc2;
                int i = i0 + ii;
                const float4* hr = (const float4*)(h3 + (long)(m0 + r) * Hn);
                const float4* wr = (const float4*)(fcW + (long)i * Hn);
                float acc = fcb[i];
                #pragma unroll
                for (int k = 0; k < 32; k++) {
                    float4 a = hr[k], b = wr[k];
                    acc = fmaf(a.x, b.x, acc); acc = fmaf(a.y, b.y, acc);
                    acc = fmaf(a.z, b.z, acc); acc = fmaf(a.w, b.w, acc);
                }
                int m = m0 + r;
                oc[(long)m * INn + i] = acc;
                dout[(long)m * Tn * INn + (long)t * INn + i] = acc;
            }
            mt_barrier(mt, &s_sense);
        }
    }
}

// ---------------------------------------------------------------------------
// Host orchestration. Launch order (ncu -s 5 captures #5 = rec layer 1):
// 0 prepA, 1 prepB, 2 pre0, 3 rec0, 4 pre1, 5 rec1, 6 pre2, 7 rec2,
// 8 pre3, 9 rec3, 10 dec.
// ---------------------------------------------------------------------------
extern "C" void kernel_launch(void* const* d_in, const int* in_sizes, int n_in,
                              void* d_out, int out_size)
{
    const float* x        = (const float*)d_in[0];
    const float* enc_Wih0 = (const float*)d_in[2];
    const float* enc_WihR = (const float*)d_in[3];
    const float* enc_Whh  = (const float*)d_in[4];
    const float* enc_b    = (const float*)d_in[5];
    const float* dec_Wih0 = (const float*)d_in[6];
    const float* dec_WihR = (const float*)d_in[7];
    const float* dec_Whh  = (const float*)d_in[8];
    const float* dec_b    = (const float*)d_in[9];
    const float* fc_W     = (const float*)d_in[10];
    const float* fc_b     = (const float*)d_in[11];
    float* out = (float*)d_out;

    float *ysA, *encC, *decH, *outb, *wpk, *P;
    __nv_bfloat16 *ysH, *ysL, *xH, *xL;
    uint32_t *bpkH, *bpkL;
    cudaGetSymbolAddress((void**)&ysA,  g_ysA);
    cudaGetSymbolAddress((void**)&ysH,  g_ysH);
    cudaGetSymbolAddress((void**)&ysL,  g_ysL);
    cudaGetSymbolAddress((void**)&xH,   g_xH);
    cudaGetSymbolAddress((void**)&xL,   g_xL);
    cudaGetSymbolAddress((void**)&P,    g_P);
    cudaGetSymbolAddress((void**)&encC, g_encC);
    cudaGetSymbolAddress((void**)&decH, g_decH);
    cudaGetSymbolAddress((void**)&outb, g_out2);
    cudaGetSymbolAddress((void**)&wpk,  g_wpk);
    cudaGetSymbolAddress((void**)&bpkH, g_bpkH);
    cudaGetSymbolAddress((void**)&bpkL, g_bpkL);

    const int smemGemm = 2 * 128 * (128 + 8) * 2;             // 69,632 B (K=128)
    cudaFuncSetAttribute(pre_gemm_kernel,
                         cudaFuncAttributeMaxDynamicSharedMemorySize, smemGemm);
    size_t smemRec = (size_t)(128 * 128 + 128 * PITCH) * 4;   // 133,120 B
    cudaFuncSetAttribute(rec_kernel,
                         cudaFuncAttributeMaxDynamicSharedMemorySize, (int)smemRec);

    // 0: fp32 packs (decoder + enc Whh)
    {
        dim3 g(512, 16);
        prepA_kernel<<<g, 256>>>(enc_Wih0, enc_WihR, enc_Whh,
                                 dec_Wih0, dec_WihR, dec_Whh, wpk);
    }
    // 1: B fragment packs + x conversion
    {
        long total = 16384 + 3L * 32768 + MROWS * 64;
        int blocks = (int)((total + 255) / 256);
        prepB_kernel<<<blocks, 256>>>(x, enc_Wih0, enc_WihR, bpkH, bpkL, xH, xL);
    }

    // encoder: pre-GEMM + recurrence per layer
    int smem0 = 2 * 128 * (64 + 8) * 2;                       // 36,864 B (K=64)
    pre_gemm_kernel<<<3200, 128, smem0>>>(xH, xL, bpkH + BPK0, bpkL + BPK0,
                                          P, 64, 4, 1);
    rec_kernel<<<128, 256, smemRec>>>(P, wpk + OFF_EHH, enc_b,
                                      ysA, ysH, ysL,
                                      decH + (long)(Ln + 0) * BH, encC);
    for (int l = 1; l < Ln; l++) {
        const uint32_t* bH = bpkH + BPKR + (long)(l - 1) * 32768;
        const uint32_t* bL = bpkL + BPKR + (long)(l - 1) * 32768;
        pre_gemm_kernel<<<3200, 128, smemGemm>>>(ysH, ysL, bH, bL, P, 128, 8, 0);
        bool needBf = (l < Ln - 1);
        rec_kernel<<<128, 256, smemRec>>>(P, wpk + OFF_EHH + (long)l * PK_128,
                                          enc_b + l * 512, ysA,
                                          needBf ? ysH : ((__nv_bfloat16*)0),
                                          needBf ? ysL : ((__nv_bfloat16*)0),
                                          decH + (long)(Ln + l) * BH,
                                          encC + (long)l * BH);
    }

    // decoder
    dec_kernel<<<128, 256>>>(x, wpk, dec_b, encC, decH, outb, fc_W, fc_b, out);
}